// round 15
// baseline (speedup 1.0000x reference)
#include <cuda_runtime.h>
#include <cstdint>

// Problem constants
#define B_   4
#define N_   2048
#define FIN  256
#define H_   4
#define FO_  64
#define HF   256               // H_*FO_
#define M_   (B_*N_)           // 8192 rows of h
#define NH   (M_*H_)           // 32768 (node, head) pairs
#define SPLIT 4                // j-dimension split factor
#define TPS  (N_ / 32 / SPLIT) // j-tiles per split segment = 16

// Scratch (device globals — no allocation allowed)
__device__ float    g_h [M_ * HF];              // h = x@W (3xTF32, ~fp32 exact)
__device__ float    g_hr[M_ * HF];              // h tf32-rounded (attention B operand)
__device__ float    g_s[NH], g_dv[NH];
__device__ float    g_A1[NH], g_A2[NH], g_E1[NH], g_E2[NH];
__device__ uint32_t g_bitsT[(N_ / 32) * N_];    // adj bitmask, transposed: [j_word][i]
__device__ float    g_pnum[B_ * H_ * 16 * SPLIT * 128 * 64];  // partial numerators
__device__ float    g_pden[B_ * H_ * 16 * SPLIT * 128];       // partial denominators

// ---------------- helpers ----------------
__device__ __forceinline__ float tf32r(float x) {   // round-to-nearest tf32 (sm_80+ baseline)
    float r; asm("cvt.rna.tf32.f32 %0, %1;" : "=f"(r) : "f"(x)); return r;
}
// m16n8k8 tf32 mma (sm_80+ baseline PTX)
__device__ __forceinline__ void mma8(float* d,
                                     uint32_t a0, uint32_t a1, uint32_t a2, uint32_t a3,
                                     uint32_t b0, uint32_t b1) {
    asm volatile(
        "mma.sync.aligned.m16n8k8.row.col.f32.tf32.tf32.f32 "
        "{%0,%1,%2,%3}, {%4,%5,%6,%7}, {%8,%9}, {%0,%1,%2,%3};"
        : "+f"(d[0]), "+f"(d[1]), "+f"(d[2]), "+f"(d[3])
        : "r"(a0), "r"(a1), "r"(a2), "r"(a3), "r"(b0), "r"(b1));
}
__device__ __forceinline__ uint32_t fbits(float x) { return __float_as_uint(x); }

// ---------------- Kernel 0: pack adj into transposed bitmask ----------------
__global__ __launch_bounds__(256) void adj_pack_kernel(const float* __restrict__ adj) {
    const int wid  = (blockIdx.x * blockDim.x + threadIdx.x) >> 5;   // row i
    const int lane = threadIdx.x & 31;
    if (wid >= N_) return;
    const float* row = adj + (size_t)wid * N_;
#pragma unroll 4
    for (int jw = 0; jw < N_ / 32; jw++) {
        const uint32_t m = __ballot_sync(0xffffffffu, row[jw * 32 + lane] != 0.f);
        if (lane == 0) g_bitsT[jw * N_ + wid] = m;
    }
}

// ---------------- Kernel 1: h = x @ W via 3xTF32 mma (R12, proven) ----------------
__global__ __launch_bounds__(256) void gemm_mma(const float* __restrict__ x,
                                                const float* __restrict__ W) {
    __shared__ float xh[16][136], xl[16][136];   // [k][m]
    __shared__ float wh[16][72],  wl[16][72];    // [k][n]

    const int t    = threadIdx.x;
    const int wi   = t >> 5;
    const int lane = t & 31;
    const int g    = lane >> 2;
    const int c    = lane & 3;
    const int m0   = blockIdx.x * 128;
    const int n0   = blockIdx.y * 64;
    const int mb   = wi * 16;

    float D[8][4];
#pragma unroll
    for (int nt = 0; nt < 8; nt++)
#pragma unroll
        for (int q = 0; q < 4; q++) D[nt][q] = 0.f;

    const int xrow = t >> 1, xoff = (t & 1) * 8;
    const int wrow = t >> 4, wcol = (t & 15) * 4;

    for (int k0 = 0; k0 < FIN; k0 += 16) {
        float4 xv0 = *(const float4*)(x + (size_t)(m0 + xrow) * FIN + k0 + xoff);
        float4 xv1 = *(const float4*)(x + (size_t)(m0 + xrow) * FIN + k0 + xoff + 4);
        float4 wv  = *(const float4*)(W + (size_t)(k0 + wrow) * HF + n0 + wcol);

        __syncthreads();
        {
            const float* xf0 = (const float*)&xv0;
            const float* xf1 = (const float*)&xv1;
#pragma unroll
            for (int q = 0; q < 4; q++) {
                float f = xf0[q], h = tf32r(f);
                xh[xoff + q][xrow] = h; xl[xoff + q][xrow] = f - h;
            }
#pragma unroll
            for (int q = 0; q < 4; q++) {
                float f = xf1[q], h = tf32r(f);
                xh[xoff + 4 + q][xrow] = h; xl[xoff + 4 + q][xrow] = f - h;
            }
            const float* wf = (const float*)&wv;
#pragma unroll
            for (int q = 0; q < 4; q++) {
                float f = wf[q], h = tf32r(f);
                wh[wrow][wcol + q] = h; wl[wrow][wcol + q] = f - h;
            }
        }
        __syncthreads();

#pragma unroll
        for (int kk2 = 0; kk2 < 2; kk2++) {
            const int kb = kk2 * 8;
            const uint32_t ah0 = fbits(xh[kb + c    ][mb + g]);
            const uint32_t ah1 = fbits(xh[kb + c    ][mb + g + 8]);
            const uint32_t ah2 = fbits(xh[kb + c + 4][mb + g]);
            const uint32_t ah3 = fbits(xh[kb + c + 4][mb + g + 8]);
            const uint32_t al0 = fbits(xl[kb + c    ][mb + g]);
            const uint32_t al1 = fbits(xl[kb + c    ][mb + g + 8]);
            const uint32_t al2 = fbits(xl[kb + c + 4][mb + g]);
            const uint32_t al3 = fbits(xl[kb + c + 4][mb + g + 8]);
#pragma unroll
            for (int nt = 0; nt < 8; nt++) {
                const uint32_t bh0 = fbits(wh[kb + c    ][nt * 8 + g]);
                const uint32_t bh1 = fbits(wh[kb + c + 4][nt * 8 + g]);
                const uint32_t bl0 = fbits(wl[kb + c    ][nt * 8 + g]);
                const uint32_t bl1 = fbits(wl[kb + c + 4][nt * 8 + g]);
                mma8(D[nt], ah0, ah1, ah2, ah3, bh0, bh1);
                mma8(D[nt], ah0, ah1, ah2, ah3, bl0, bl1);
                mma8(D[nt], al0, al1, al2, al3, bh0, bh1);
            }
        }
    }

#pragma unroll
    for (int nt = 0; nt < 8; nt++) {
        const size_t r0 = (size_t)(m0 + mb + g)     * HF + n0 + nt * 8 + c * 2;
        const size_t r1 = (size_t)(m0 + mb + g + 8) * HF + n0 + nt * 8 + c * 2;
        *(float2*)(g_h  + r0) = make_float2(D[nt][0], D[nt][1]);
        *(float2*)(g_h  + r1) = make_float2(D[nt][2], D[nt][3]);
        *(float2*)(g_hr + r0) = make_float2(tf32r(D[nt][0]), tf32r(D[nt][1]));
        *(float2*)(g_hr + r1) = make_float2(tf32r(D[nt][2]), tf32r(D[nt][3]));
    }
}

// ---------------- Kernel 2: attention coefficients + exp factors ----------------
__global__ __launch_bounds__(256) void attn_coef_kernel(const float* __restrict__ a_src,
                                                        const float* __restrict__ a_dst) {
    const int nh   = (blockIdx.x * blockDim.x + threadIdx.x) >> 5;
    const int lane = threadIdx.x & 31;
    if (nh >= NH) return;
    const int head = nh & (H_ - 1);

    const float* hrow = g_h + (size_t)nh * FO_;
    const float v0 = hrow[lane];
    const float v1 = hrow[lane + 32];
    const float* as = a_src + head * FO_;
    const float* ad = a_dst + head * FO_;
    float ps = v0 * as[lane] + v1 * as[lane + 32];
    float pd = v0 * ad[lane] + v1 * ad[lane + 32];
#pragma unroll
    for (int o = 16; o > 0; o >>= 1) {
        ps += __shfl_xor_sync(0xffffffffu, ps, o);
        pd += __shfl_xor_sync(0xffffffffu, pd, o);
    }
    if (lane == 0) {
        g_s[nh]  = ps;
        g_A1[nh] = expf(ps);
        g_A2[nh] = expf(0.2f * ps);
        g_dv[nh] = pd;
        g_E1[nh] = expf(pd);
        g_E2[nh] = expf(0.2f * pd);
    }
}

// ---------------- Kernel 3: split-j mma.sync tf32 attention (lean-register) ----------------
// Block = (i-block 128, head, b*SPLIT + seg), 128 threads = 4 warps.
// No ones-column: denominator accumulates in fp32 regs during weight generation,
// reduced across the 4 c-lanes with shfl_xor at the epilogue.
// Weight generation is merged into the k-step loop (8 transient weights per s)
// to minimize live registers -> target 4 CTAs/SM.
#define TJ  32
#define HSW 73

__global__ __launch_bounds__(128, 4) void gat_attn_mma(void) {
    __shared__ float h_s[TJ][HSW];
    __shared__ __align__(16) float4 de_s[TJ];
    __shared__ uint32_t bm_s[128];

    const int t    = threadIdx.x;
    const int wi   = t >> 5;
    const int lane = t & 31;
    const int g    = lane >> 2;    // groupID 0..7
    const int c    = lane & 3;     // threadID_in_group 0..3
    const int ib   = blockIdx.x;
    const int head = blockIdx.y;
    const int b    = blockIdx.z >> 2;     // SPLIT = 4
    const int seg  = blockIdx.z & 3;
    const int jt0  = seg * TPS;

    // per-thread row coefficients: rr -> row wi*32 + (rr>>1)*16 + (rr&1)*8 + g
    float si[4], A1[4], A2[4], denom[4];
#pragma unroll
    for (int rr = 0; rr < 4; rr++) {
        const int row = ib * 128 + wi * 32 + (rr >> 1) * 16 + (rr & 1) * 8 + g;
        const int nh  = (b * N_ + row) * H_ + head;
        si[rr] = g_s[nh]; A1[rr] = g_A1[nh]; A2[rr] = g_A2[nh];
        denom[rr] = 0.f;
    }

    float D[2][8][4];
#pragma unroll
    for (int mt = 0; mt < 2; mt++)
#pragma unroll
        for (int nt = 0; nt < 8; nt++)
#pragma unroll
            for (int q = 0; q < 4; q++) D[mt][nt][q] = 0.f;

    const float* hbase = g_hr + (size_t)(b * N_) * HF + head * FO_;

    const int jr = t >> 2;          // h row 0..31
    const int jc = (t & 3) * 16;    // h col group

    // prologue: prefetch first tile of this segment
    uint32_t bmr;
    float4 hb[4];
    float nd = 0.f, ne1 = 0.f, ne2 = 0.f;
    {
        bmr = g_bitsT[jt0 * N_ + ib * 128 + t];
        const int j0 = jt0 * TJ;
#pragma unroll
        for (int q = 0; q < 4; q++)
            hb[q] = *(const float4*)(hbase + (size_t)(j0 + jr) * HF + jc + 4 * q);
        if (t < TJ) {
            const int nh_j = (b * N_ + j0 + t) * H_ + head;
            nd = g_dv[nh_j]; ne1 = g_E1[nh_j]; ne2 = g_E2[nh_j];
        }
    }

    for (int jl = 0; jl < TPS; jl++) {
        const int jt = jt0 + jl;
        __syncthreads();   // previous tile's compute done reading smem
        bm_s[t] = bmr;
#pragma unroll
        for (int q = 0; q < 4; q++) {
            h_s[jr][jc + 4 * q + 0] = ((const float*)&hb[q])[0];
            h_s[jr][jc + 4 * q + 1] = ((const float*)&hb[q])[1];
            h_s[jr][jc + 4 * q + 2] = ((const float*)&hb[q])[2];
            h_s[jr][jc + 4 * q + 3] = ((const float*)&hb[q])[3];
        }
        if (t < TJ) de_s[t] = make_float4(nd, ne1, ne2, 0.f);
        __syncthreads();

        // prefetch next tile (LDG latency hidden under compute)
        if (jl + 1 < TPS) {
            const int j0 = (jt + 1) * TJ;
            bmr = g_bitsT[(jt + 1) * N_ + ib * 128 + t];
#pragma unroll
            for (int q = 0; q < 4; q++)
                hb[q] = *(const float4*)(hbase + (size_t)(j0 + jr) * HF + jc + 4 * q);
            if (t < TJ) {
                const int nh_j = (b * N_ + j0 + t) * H_ + head;
                nd = g_dv[nh_j]; ne1 = g_E1[nh_j]; ne2 = g_E2[nh_j];
            }
        }

        // bitmask words for this thread's 4 rows (bits for j = c*8 + u)
        uint32_t bmv[4];
#pragma unroll
        for (int rr = 0; rr < 4; rr++) {
            const int rl = wi * 32 + (rr >> 1) * 16 + (rr & 1) * 8 + g;
            bmv[rr] = bm_s[rl] >> (c * 8);
        }

        // ---- merged weight-gen + mma, per k-step s (j pair = c*8+2s, c*8+2s+1) ----
#pragma unroll
        for (int s = 0; s < 4; s++) {
            const float4 de0 = de_s[c * 8 + 2 * s];
            const float4 de1 = de_s[c * 8 + 2 * s + 1];
            float w0[4], w1[4];
#pragma unroll
            for (int rr = 0; rr < 4; rr++) {
                const float t0 = si[rr] + de0.x;
                float a = (t0 > 0.f) ? (A1[rr] * de0.y) : (A2[rr] * de0.z);
                a = ((bmv[rr] >> (2 * s)) & 1u) ? a : 0.f;
                w0[rr] = tf32r(a);
                const float t1 = si[rr] + de1.x;
                float e = (t1 > 0.f) ? (A1[rr] * de1.y) : (A2[rr] * de1.z);
                e = ((bmv[rr] >> (2 * s + 1)) & 1u) ? e : 0.f;
                w1[rr] = tf32r(e);
                denom[rr] += w0[rr] + w1[rr];
            }
            const uint32_t a00 = fbits(w0[0]);
            const uint32_t a01 = fbits(w0[1]);
            const uint32_t a02 = fbits(w1[0]);
            const uint32_t a03 = fbits(w1[1]);
            const uint32_t a10 = fbits(w0[2]);
            const uint32_t a11 = fbits(w0[3]);
            const uint32_t a12 = fbits(w1[2]);
            const uint32_t a13 = fbits(w1[3]);
            const float* hr0 = &h_s[c * 8 + 2 * s][g];
            const float* hr1 = &h_s[c * 8 + 2 * s + 1][g];
#pragma unroll
            for (int nt = 0; nt < 8; nt++) {
                const uint32_t b0 = fbits(hr0[nt * 8]);
                const uint32_t b1 = fbits(hr1[nt * 8]);
                mma8(D[0][nt], a00, a01, a02, a03, b0, b1);
                mma8(D[1][nt], a10, a11, a12, a13, b0, b1);
            }
        }
    }

    // ---- epilogue: reduce denominators across c-lanes, write partials ----
    const int pidx = ((b * H_ + head) * 16 + ib) * SPLIT + seg;
    float* pnum = g_pnum + (size_t)pidx * (128 * 64);
    float* pden = g_pden + (size_t)pidx * 128;

#pragma unroll
    for (int rr = 0; rr < 4; rr++) {
        denom[rr] += __shfl_xor_sync(0xffffffffu, denom[rr], 1);
        denom[rr] += __shfl_xor_sync(0xffffffffu, denom[rr], 2);
        if (c == 0) {
            const int rl = wi * 32 + (rr >> 1) * 16 + (rr & 1) * 8 + g;
            pden[rl] = denom[rr];
        }
    }

#pragma unroll
    for (int mt = 0; mt < 2; mt++)
#pragma unroll
        for (int hi = 0; hi < 2; hi++) {
            const int rl = wi * 32 + mt * 16 + hi * 8 + g;
            float* prow  = pnum + (size_t)rl * 64;
#pragma unroll
            for (int nt = 0; nt < 8; nt++) {
                float2 v;
                v.x = D[mt][nt][hi * 2];
                v.y = D[mt][nt][hi * 2 + 1];
                *(float2*)(prow + nt * 8 + 2 * c) = v;
            }
        }
}

// ---------------- Kernel 4: combine split partials + normalize ----------------
__global__ __launch_bounds__(256) void gat_combine(float* __restrict__ out) {
    const int t    = threadIdx.x;
    const int ib   = blockIdx.x;
    const int head = blockIdx.y;
    const int b    = blockIdx.z;
    const int row  = t >> 1;
    const int ch   = (t & 1) * 32;

    const int base = ((b * H_ + head) * 16 + ib) * SPLIT;

    float den = 0.f;
#pragma unroll
    for (int s = 0; s < SPLIT; s++)
        den += g_pden[(size_t)(base + s) * 128 + row];
    const float r = 1.0f / den;

    float4 acc[8];
#pragma unroll
    for (int q = 0; q < 8; q++) acc[q] = make_float4(0.f, 0.f, 0.f, 0.f);
#pragma unroll
    for (int s = 0; s < SPLIT; s++) {
        const float4* p = (const float4*)(g_pnum + (size_t)(base + s) * (128 * 64)
                                          + (size_t)row * 64 + ch);
#pragma unroll
        for (int q = 0; q < 8; q++) {
            const float4 v = p[q];
            acc[q].x += v.x; acc[q].y += v.y; acc[q].z += v.z; acc[q].w += v.w;
        }
    }

    float* orow = out + (size_t)(b * N_ + ib * 128 + row) * HF + head * FO_ + ch;
#pragma unroll
    for (int q = 0; q < 8; q++)
        *(float4*)(orow + 4 * q) = make_float4(acc[q].x * r, acc[q].y * r,
                                               acc[q].z * r, acc[q].w * r);
}

// ---------------- launch ----------------
extern "C" void kernel_launch(void* const* d_in, const int* in_sizes, int n_in,
                              void* d_out, int out_size) {
    (void)in_sizes; (void)n_in; (void)out_size;
    const float* x     = (const float*)d_in[0];
    const float* adj   = (const float*)d_in[1];
    const float* W     = (const float*)d_in[2];
    const float* a_src = (const float*)d_in[3];
    const float* a_dst = (const float*)d_in[4];
    float* out = (float*)d_out;

    adj_pack_kernel<<<(N_ * 32) / 256, 256>>>(adj);
    gemm_mma<<<dim3(M_ / 128, HF / 64), 256>>>(x, W);
    attn_coef_kernel<<<(NH * 32) / 256, 256>>>(a_src, a_dst);
    gat_attn_mma<<<dim3(N_ / 128, H_, B_ * SPLIT), 128>>>();
    gat_combine<<<dim3(16, H_, B_), 256>>>(out);
}

// round 16
// speedup vs baseline: 1.1518x; 1.1518x over previous
#include <cuda_runtime.h>
#include <cstdint>

// Problem constants
#define B_   4
#define N_   2048
#define FIN  256
#define H_   4
#define FO_  64
#define HF   256               // H_*FO_
#define M_   (B_*N_)           // 8192 rows of h
#define NH   (M_*H_)           // 32768 (node, head) pairs
#define SPLIT 4                // j-dimension split factor
#define TPS  (N_ / 32 / SPLIT) // j-tiles per split segment = 16

// Scratch (device globals — no allocation allowed)
__device__ float    g_h  [M_ * HF];             // h = x@W (3xTF32, ~fp32 exact)
__device__ float    g_hTr[B_ * H_ * FO_ * N_];  // h transposed per (b,head): [f][j], tf32-rounded
__device__ float    g_s[NH], g_dv[NH];
__device__ float    g_A1[NH], g_A2[NH], g_E1[NH], g_E2[NH];
__device__ uint32_t g_bitsT[(N_ / 32) * N_];    // adj bitmask, transposed: [j_word][i]
__device__ float    g_pnum[B_ * H_ * 16 * SPLIT * 128 * 64];  // partial numerators
__device__ float    g_pden[B_ * H_ * 16 * SPLIT * 128];       // partial denominators

// ---------------- helpers ----------------
__device__ __forceinline__ float tf32r(float x) {   // round-to-nearest tf32 (sm_80+ baseline)
    float r; asm("cvt.rna.tf32.f32 %0, %1;" : "=f"(r) : "f"(x)); return r;
}
// m16n8k8 tf32 mma (sm_80+ baseline PTX)
__device__ __forceinline__ void mma8(float* d,
                                     uint32_t a0, uint32_t a1, uint32_t a2, uint32_t a3,
                                     uint32_t b0, uint32_t b1) {
    asm volatile(
        "mma.sync.aligned.m16n8k8.row.col.f32.tf32.tf32.f32 "
        "{%0,%1,%2,%3}, {%4,%5,%6,%7}, {%8,%9}, {%0,%1,%2,%3};"
        : "+f"(d[0]), "+f"(d[1]), "+f"(d[2]), "+f"(d[3])
        : "r"(a0), "r"(a1), "r"(a2), "r"(a3), "r"(b0), "r"(b1));
}
__device__ __forceinline__ uint32_t fbits(float x) { return __float_as_uint(x); }

// ---------------- Kernel 0: pack adj into transposed bitmask ----------------
__global__ __launch_bounds__(256) void adj_pack_kernel(const float* __restrict__ adj) {
    const int wid  = (blockIdx.x * blockDim.x + threadIdx.x) >> 5;   // row i
    const int lane = threadIdx.x & 31;
    if (wid >= N_) return;
    const float* row = adj + (size_t)wid * N_;
#pragma unroll 4
    for (int jw = 0; jw < N_ / 32; jw++) {
        const uint32_t m = __ballot_sync(0xffffffffu, row[jw * 32 + lane] != 0.f);
        if (lane == 0) g_bitsT[jw * N_ + wid] = m;
    }
}

// ---------------- Kernel 1: h = x @ W via 3xTF32 mma ----------------
// Epilogue writes g_h (normal, fp32 exact) + g_hTr (transposed, tf32-rounded).
__global__ __launch_bounds__(256) void gemm_mma(const float* __restrict__ x,
                                                const float* __restrict__ W) {
    __shared__ float xh[16][136], xl[16][136];   // [k][m]
    __shared__ float wh[16][72],  wl[16][72];    // [k][n]

    const int t    = threadIdx.x;
    const int wi   = t >> 5;
    const int lane = t & 31;
    const int g    = lane >> 2;
    const int c    = lane & 3;
    const int m0   = blockIdx.x * 128;
    const int n0   = blockIdx.y * 64;
    const int mb   = wi * 16;

    float D[8][4];
#pragma unroll
    for (int nt = 0; nt < 8; nt++)
#pragma unroll
        for (int q = 0; q < 4; q++) D[nt][q] = 0.f;

    const int xrow = t >> 1, xoff = (t & 1) * 8;
    const int wrow = t >> 4, wcol = (t & 15) * 4;

    for (int k0 = 0; k0 < FIN; k0 += 16) {
        float4 xv0 = *(const float4*)(x + (size_t)(m0 + xrow) * FIN + k0 + xoff);
        float4 xv1 = *(const float4*)(x + (size_t)(m0 + xrow) * FIN + k0 + xoff + 4);
        float4 wv  = *(const float4*)(W + (size_t)(k0 + wrow) * HF + n0 + wcol);

        __syncthreads();
        {
            const float* xf0 = (const float*)&xv0;
            const float* xf1 = (const float*)&xv1;
#pragma unroll
            for (int q = 0; q < 4; q++) {
                float f = xf0[q], h = tf32r(f);
                xh[xoff + q][xrow] = h; xl[xoff + q][xrow] = f - h;
            }
#pragma unroll
            for (int q = 0; q < 4; q++) {
                float f = xf1[q], h = tf32r(f);
                xh[xoff + 4 + q][xrow] = h; xl[xoff + 4 + q][xrow] = f - h;
            }
            const float* wf = (const float*)&wv;
#pragma unroll
            for (int q = 0; q < 4; q++) {
                float f = wf[q], h = tf32r(f);
                wh[wrow][wcol + q] = h; wl[wrow][wcol + q] = f - h;
            }
        }
        __syncthreads();

#pragma unroll
        for (int kk2 = 0; kk2 < 2; kk2++) {
            const int kb = kk2 * 8;
            const uint32_t ah0 = fbits(xh[kb + c    ][mb + g]);
            const uint32_t ah1 = fbits(xh[kb + c    ][mb + g + 8]);
            const uint32_t ah2 = fbits(xh[kb + c + 4][mb + g]);
            const uint32_t ah3 = fbits(xh[kb + c + 4][mb + g + 8]);
            const uint32_t al0 = fbits(xl[kb + c    ][mb + g]);
            const uint32_t al1 = fbits(xl[kb + c    ][mb + g + 8]);
            const uint32_t al2 = fbits(xl[kb + c + 4][mb + g]);
            const uint32_t al3 = fbits(xl[kb + c + 4][mb + g + 8]);
#pragma unroll
            for (int nt = 0; nt < 8; nt++) {
                const uint32_t bh0 = fbits(wh[kb + c    ][nt * 8 + g]);
                const uint32_t bh1 = fbits(wh[kb + c + 4][nt * 8 + g]);
                const uint32_t bl0 = fbits(wl[kb + c    ][nt * 8 + g]);
                const uint32_t bl1 = fbits(wl[kb + c + 4][nt * 8 + g]);
                mma8(D[nt], ah0, ah1, ah2, ah3, bh0, bh1);
                mma8(D[nt], ah0, ah1, ah2, ah3, bl0, bl1);
                mma8(D[nt], al0, al1, al2, al3, bh0, bh1);
            }
        }
    }

    // epilogue: normal g_h + transposed tf32-rounded g_hTr
    const int bq   = m0 / N_;            // batch
    const int head = blockIdx.y;         // n0 = head*64
    const int nb   = (m0 % N_) + mb;     // node base for this warp
    float* hTb = g_hTr + (size_t)((bq * H_ + head) * FO_) * N_;

#pragma unroll
    for (int nt = 0; nt < 8; nt++) {
        const size_t r0 = (size_t)(m0 + mb + g)     * HF + n0 + nt * 8 + c * 2;
        const size_t r1 = (size_t)(m0 + mb + g + 8) * HF + n0 + nt * 8 + c * 2;
        *(float2*)(g_h + r0) = make_float2(D[nt][0], D[nt][1]);
        *(float2*)(g_h + r1) = make_float2(D[nt][2], D[nt][3]);

        const int f0 = nt * 8 + c * 2;
        hTb[(size_t)(f0)     * N_ + nb + g]     = tf32r(D[nt][0]);
        hTb[(size_t)(f0 + 1) * N_ + nb + g]     = tf32r(D[nt][1]);
        hTb[(size_t)(f0)     * N_ + nb + g + 8] = tf32r(D[nt][2]);
        hTb[(size_t)(f0 + 1) * N_ + nb + g + 8] = tf32r(D[nt][3]);
    }
}

// ---------------- Kernel 2: attention coefficients + exp factors ----------------
__global__ __launch_bounds__(256) void attn_coef_kernel(const float* __restrict__ a_src,
                                                        const float* __restrict__ a_dst) {
    const int nh   = (blockIdx.x * blockDim.x + threadIdx.x) >> 5;
    const int lane = threadIdx.x & 31;
    if (nh >= NH) return;
    const int head = nh & (H_ - 1);

    const float* hrow = g_h + (size_t)nh * FO_;
    const float v0 = hrow[lane];
    const float v1 = hrow[lane + 32];
    const float* as = a_src + head * FO_;
    const float* ad = a_dst + head * FO_;
    float ps = v0 * as[lane] + v1 * as[lane + 32];
    float pd = v0 * ad[lane] + v1 * ad[lane + 32];
#pragma unroll
    for (int o = 16; o > 0; o >>= 1) {
        ps += __shfl_xor_sync(0xffffffffu, ps, o);
        pd += __shfl_xor_sync(0xffffffffu, pd, o);
    }
    if (lane == 0) {
        g_s[nh]  = ps;
        g_A1[nh] = expf(ps);
        g_A2[nh] = expf(0.2f * ps);
        g_dv[nh] = pd;
        g_E1[nh] = expf(pd);
        g_E2[nh] = expf(0.2f * pd);
    }
}

// ---------------- Kernel 3: split-j mma.sync tf32 attention (transposed B) ----------------
// Block = (i-block 128, head, b*SPLIT + seg), 128 threads = 4 warps.
// h-tile stored TRANSPOSED: h_sT[f][j] -> B-fragments come as LDS.128 (4 j's =
// 2 k-steps per load). Denominator = 9th mma with constant-1 B operands (exact
// consistency with numerator, zero LDS). Phase B batch-computes weights (R14).
#define TJ  32
#define HST 36     // h_sT row stride (floats): 32 j + 4 pad; f-row delta = 4 banks

__global__ __launch_bounds__(128, 3) void gat_attn_mma(void) {
    __shared__ __align__(16) float h_sT[64][HST];
    __shared__ __align__(16) float4 de_s[TJ];
    __shared__ uint32_t bm_s[128];

    const int t    = threadIdx.x;
    const int wi   = t >> 5;
    const int lane = t & 31;
    const int g    = lane >> 2;    // groupID 0..7
    const int c    = lane & 3;     // threadID_in_group 0..3
    const int ib   = blockIdx.x;
    const int head = blockIdx.y;
    const int b    = blockIdx.z >> 2;     // SPLIT = 4
    const int seg  = blockIdx.z & 3;
    const int jt0  = seg * TPS;

    // per-thread row coefficients: rr -> row wi*32 + (rr>>1)*16 + (rr&1)*8 + g
    float si[4], A1[4], A2[4];
#pragma unroll
    for (int rr = 0; rr < 4; rr++) {
        const int row = ib * 128 + wi * 32 + (rr >> 1) * 16 + (rr & 1) * 8 + g;
        const int nh  = (b * N_ + row) * H_ + head;
        si[rr] = g_s[nh]; A1[rr] = g_A1[nh]; A2[rr] = g_A2[nh];
    }

    float D[2][9][4];
#pragma unroll
    for (int mt = 0; mt < 2; mt++)
#pragma unroll
        for (int nt = 0; nt < 9; nt++)
#pragma unroll
            for (int q = 0; q < 4; q++) D[mt][nt][q] = 0.f;

    const float* hTb = g_hTr + (size_t)((b * H_ + head) * FO_) * N_;

    // transposed staging map: thread t -> f rows (t>>3)+16k, j-quad (t&7)*4
    const int fr = t >> 3;
    const int jq = (t & 7) * 4;

    // prologue: prefetch first tile of this segment
    uint32_t bmr;
    float4 hb[4];
    float nd = 0.f, ne1 = 0.f, ne2 = 0.f;
    {
        bmr = g_bitsT[jt0 * N_ + ib * 128 + t];
        const int j0 = jt0 * TJ;
#pragma unroll
        for (int k = 0; k < 4; k++)
            hb[k] = *(const float4*)(hTb + (size_t)(fr + 16 * k) * N_ + j0 + jq);
        if (t < TJ) {
            const int nh_j = (b * N_ + j0 + t) * H_ + head;
            nd = g_dv[nh_j]; ne1 = g_E1[nh_j]; ne2 = g_E2[nh_j];
        }
    }

    const uint32_t ONE = 0x3f800000u;

    for (int jl = 0; jl < TPS; jl++) {
        const int jt = jt0 + jl;
        __syncthreads();   // previous tile's compute done reading smem
        bm_s[t] = bmr;
#pragma unroll
        for (int k = 0; k < 4; k++)
            *(float4*)&h_sT[fr + 16 * k][jq] = hb[k];
        if (t < TJ) de_s[t] = make_float4(nd, ne1, ne2, 0.f);
        __syncthreads();

        // prefetch next tile (LDG latency hidden under Phase B + mma)
        if (jl + 1 < TPS) {
            const int j0 = (jt + 1) * TJ;
            bmr = g_bitsT[(jt + 1) * N_ + ib * 128 + t];
#pragma unroll
            for (int k = 0; k < 4; k++)
                hb[k] = *(const float4*)(hTb + (size_t)(fr + 16 * k) * N_ + j0 + jq);
            if (t < TJ) {
                const int nh_j = (b * N_ + j0 + t) * H_ + head;
                nd = g_dv[nh_j]; ne1 = g_E1[nh_j]; ne2 = g_E2[nh_j];
            }
        }

        // ---- Phase B: factored weights into A-fragment registers (R14 style) ----
        float4 der[8];
#pragma unroll
        for (int u = 0; u < 8; u++) der[u] = de_s[c * 8 + u];

        float wv[4][8];
#pragma unroll
        for (int rr = 0; rr < 4; rr++) {
            const int rl = wi * 32 + (rr >> 1) * 16 + (rr & 1) * 8 + g;
            const uint32_t m = bm_s[rl] >> (c * 8);
#pragma unroll
            for (int u = 0; u < 8; u++) {
                const float t0 = si[rr] + der[u].x;
                float w = (t0 > 0.f) ? (A1[rr] * der[u].y) : (A2[rr] * der[u].z);
                w = ((m >> u) & 1u) ? w : 0.f;
                wv[rr][u] = tf32r(w);
            }
        }

        // ---- mma phase: p covers k-steps s=2p, 2p+1 with ONE LDS.128 per nt ----
#pragma unroll
        for (int p = 0; p < 2; p++) {
            // s0 = 2p  -> j = c*8 + 4p + {0,1}
            const uint32_t s0a00 = fbits(wv[0][4 * p]);
            const uint32_t s0a01 = fbits(wv[1][4 * p]);
            const uint32_t s0a02 = fbits(wv[0][4 * p + 1]);
            const uint32_t s0a03 = fbits(wv[1][4 * p + 1]);
            const uint32_t s0a10 = fbits(wv[2][4 * p]);
            const uint32_t s0a11 = fbits(wv[3][4 * p]);
            const uint32_t s0a12 = fbits(wv[2][4 * p + 1]);
            const uint32_t s0a13 = fbits(wv[3][4 * p + 1]);
            // s1 = 2p+1 -> j = c*8 + 4p + {2,3}
            const uint32_t s1a00 = fbits(wv[0][4 * p + 2]);
            const uint32_t s1a01 = fbits(wv[1][4 * p + 2]);
            const uint32_t s1a02 = fbits(wv[0][4 * p + 3]);
            const uint32_t s1a03 = fbits(wv[1][4 * p + 3]);
            const uint32_t s1a10 = fbits(wv[2][4 * p + 2]);
            const uint32_t s1a11 = fbits(wv[3][4 * p + 2]);
            const uint32_t s1a12 = fbits(wv[2][4 * p + 3]);
            const uint32_t s1a13 = fbits(wv[3][4 * p + 3]);

#pragma unroll
            for (int nt = 0; nt < 8; nt++) {
                const float4 hv = *(const float4*)&h_sT[nt * 8 + g][c * 8 + 4 * p];
                mma8(D[0][nt], s0a00, s0a01, s0a02, s0a03, fbits(hv.x), fbits(hv.y));
                mma8(D[1][nt], s0a10, s0a11, s0a12, s0a13, fbits(hv.x), fbits(hv.y));
                mma8(D[0][nt], s1a00, s1a01, s1a02, s1a03, fbits(hv.z), fbits(hv.w));
                mma8(D[1][nt], s1a10, s1a11, s1a12, s1a13, fbits(hv.z), fbits(hv.w));
            }
            // denominator: B = 1 (constant, no LDS)
            mma8(D[0][8], s0a00, s0a01, s0a02, s0a03, ONE, ONE);
            mma8(D[1][8], s0a10, s0a11, s0a12, s0a13, ONE, ONE);
            mma8(D[0][8], s1a00, s1a01, s1a02, s1a03, ONE, ONE);
            mma8(D[1][8], s1a10, s1a11, s1a12, s1a13, ONE, ONE);
        }
    }

    // ---- epilogue: write UNNORMALIZED partials to scratch ----
    const int pidx = ((b * H_ + head) * 16 + ib) * SPLIT + seg;
    float* pnum = g_pnum + (size_t)pidx * (128 * 64);
    float* pden = g_pden + (size_t)pidx * 128;

    if (c == 0) {
        pden[wi * 32 + g]      = D[0][8][0];
        pden[wi * 32 + g + 8]  = D[0][8][2];
        pden[wi * 32 + 16 + g] = D[1][8][0];
        pden[wi * 32 + 24 + g] = D[1][8][2];
    }

#pragma unroll
    for (int mt = 0; mt < 2; mt++)
#pragma unroll
        for (int hi = 0; hi < 2; hi++) {
            const int rl = wi * 32 + mt * 16 + hi * 8 + g;
            float* prow  = pnum + (size_t)rl * 64;
#pragma unroll
            for (int nt = 0; nt < 8; nt++) {
                float2 v;
                v.x = D[mt][nt][hi * 2];
                v.y = D[mt][nt][hi * 2 + 1];
                *(float2*)(prow + nt * 8 + 2 * c) = v;
            }
        }
}

// ---------------- Kernel 4: combine split partials + normalize ----------------
__global__ __launch_bounds__(256) void gat_combine(float* __restrict__ out) {
    const int t    = threadIdx.x;
    const int ib   = blockIdx.x;
    const int head = blockIdx.y;
    const int b    = blockIdx.z;
    const int row  = t >> 1;
    const int ch   = (t & 1) * 32;

    const int base = ((b * H_ + head) * 16 + ib) * SPLIT;

    float den = 0.f;
#pragma unroll
    for (int s = 0; s < SPLIT; s++)
        den += g_pden[(size_t)(base + s) * 128 + row];
    const float r = 1.0f / den;

    float4 acc[8];
#pragma unroll
    for (int q = 0; q < 8; q++) acc[q] = make_float4(0.f, 0.f, 0.f, 0.f);
#pragma unroll
    for (int s = 0; s < SPLIT; s++) {
        const float4* p = (const float4*)(g_pnum + (size_t)(base + s) * (128 * 64)
                                          + (size_t)row * 64 + ch);
#pragma unroll
        for (int q = 0; q < 8; q++) {
            const float4 v = p[q];
            acc[q].x += v.x; acc[q].y += v.y; acc[q].z += v.z; acc[q].w += v.w;
        }
    }

    float* orow = out + (size_t)(b * N_ + ib * 128 + row) * HF + head * FO_ + ch;
#pragma unroll
    for (int q = 0; q < 8; q++)
        *(float4*)(orow + 4 * q) = make_float4(acc[q].x * r, acc[q].y * r,
                                               acc[q].z * r, acc[q].w * r);
}

// ---------------- launch ----------------
extern "C" void kernel_launch(void* const* d_in, const int* in_sizes, int n_in,
                              void* d_out, int out_size) {
    (void)in_sizes; (void)n_in; (void)out_size;
    const float* x     = (const float*)d_in[0];
    const float* adj   = (const float*)d_in[1];
    const float* W     = (const float*)d_in[2];
    const float* a_src = (const float*)d_in[3];
    const float* a_dst = (const float*)d_in[4];
    float* out = (float*)d_out;

    adj_pack_kernel<<<(N_ * 32) / 256, 256>>>(adj);
    gemm_mma<<<dim3(M_ / 128, HF / 64), 256>>>(x, W);
    attn_coef_kernel<<<(NH * 32) / 256, 256>>>(a_src, a_dst);
    gat_attn_mma<<<dim3(N_ / 128, H_, B_ * SPLIT), 128>>>();
    gat_combine<<<dim3(16, H_, B_), 256>>>(out);
}

// round 17
// speedup vs baseline: 1.3452x; 1.1679x over previous
#include <cuda_runtime.h>
#include <cstdint>

// Problem constants
#define B_   4
#define N_   2048
#define FIN  256
#define H_   4
#define FO_  64
#define HF   256               // H_*FO_
#define M_   (B_*N_)           // 8192 rows of h
#define NH   (M_*H_)           // 32768 (node, head) pairs
#define SPLIT 4                // j-dimension split factor
#define TPS  (N_ / 32 / SPLIT) // j-tiles per split segment = 16

// Scratch (device globals — no allocation allowed)
__device__ float    g_h  [M_ * HF];             // h = x@W (3xTF32, ~fp32 exact)
__device__ float    g_hTr[B_ * H_ * FO_ * N_];  // h transposed per (b,head): [f][j], tf32-rounded
__device__ float    g_A1[NH], g_A2[NH], g_E1[NH], g_E2[NH];
__device__ uint32_t g_bitsT[(N_ / 32) * N_];    // adj bitmask, transposed: [j_word][i]
__device__ float    g_pnum[B_ * H_ * 16 * SPLIT * 128 * 64];  // partial numerators
__device__ float    g_pden[B_ * H_ * 16 * SPLIT * 128];       // partial denominators

// ---------------- helpers ----------------
__device__ __forceinline__ float tf32r(float x) {   // round-to-nearest tf32 (sm_80+ baseline)
    float r; asm("cvt.rna.tf32.f32 %0, %1;" : "=f"(r) : "f"(x)); return r;
}
// m16n8k8 tf32 mma (sm_80+ baseline PTX)
__device__ __forceinline__ void mma8(float* d,
                                     uint32_t a0, uint32_t a1, uint32_t a2, uint32_t a3,
                                     uint32_t b0, uint32_t b1) {
    asm volatile(
        "mma.sync.aligned.m16n8k8.row.col.f32.tf32.tf32.f32 "
        "{%0,%1,%2,%3}, {%4,%5,%6,%7}, {%8,%9}, {%0,%1,%2,%3};"
        : "+f"(d[0]), "+f"(d[1]), "+f"(d[2]), "+f"(d[3])
        : "r"(a0), "r"(a1), "r"(a2), "r"(a3), "r"(b0), "r"(b1));
}
__device__ __forceinline__ uint32_t fbits(float x) { return __float_as_uint(x); }

// ---------------- Kernel 0: pack adj into transposed bitmask ----------------
__global__ __launch_bounds__(256) void adj_pack_kernel(const float* __restrict__ adj) {
    const int wid  = (blockIdx.x * blockDim.x + threadIdx.x) >> 5;   // row i
    const int lane = threadIdx.x & 31;
    if (wid >= N_) return;
    const float* row = adj + (size_t)wid * N_;
#pragma unroll 4
    for (int jw = 0; jw < N_ / 32; jw++) {
        const uint32_t m = __ballot_sync(0xffffffffu, row[jw * 32 + lane] != 0.f);
        if (lane == 0) g_bitsT[jw * N_ + wid] = m;
    }
}

// ---------------- Kernel 1: h = x @ W via 3xTF32 mma ----------------
// Epilogue writes g_h (normal, fp32 exact) + g_hTr (transposed, tf32-rounded).
__global__ __launch_bounds__(256) void gemm_mma(const float* __restrict__ x,
                                                const float* __restrict__ W) {
    __shared__ float xh[16][136], xl[16][136];   // [k][m]
    __shared__ float wh[16][72],  wl[16][72];    // [k][n]

    const int t    = threadIdx.x;
    const int wi   = t >> 5;
    const int lane = t & 31;
    const int g    = lane >> 2;
    const int c    = lane & 3;
    const int m0   = blockIdx.x * 128;
    const int n0   = blockIdx.y * 64;
    const int mb   = wi * 16;

    float D[8][4];
#pragma unroll
    for (int nt = 0; nt < 8; nt++)
#pragma unroll
        for (int q = 0; q < 4; q++) D[nt][q] = 0.f;

    const int xrow = t >> 1, xoff = (t & 1) * 8;
    const int wrow = t >> 4, wcol = (t & 15) * 4;

    for (int k0 = 0; k0 < FIN; k0 += 16) {
        float4 xv0 = *(const float4*)(x + (size_t)(m0 + xrow) * FIN + k0 + xoff);
        float4 xv1 = *(const float4*)(x + (size_t)(m0 + xrow) * FIN + k0 + xoff + 4);
        float4 wv  = *(const float4*)(W + (size_t)(k0 + wrow) * HF + n0 + wcol);

        __syncthreads();
        {
            const float* xf0 = (const float*)&xv0;
            const float* xf1 = (const float*)&xv1;
#pragma unroll
            for (int q = 0; q < 4; q++) {
                float f = xf0[q], h = tf32r(f);
                xh[xoff + q][xrow] = h; xl[xoff + q][xrow] = f - h;
            }
#pragma unroll
            for (int q = 0; q < 4; q++) {
                float f = xf1[q], h = tf32r(f);
                xh[xoff + 4 + q][xrow] = h; xl[xoff + 4 + q][xrow] = f - h;
            }
            const float* wf = (const float*)&wv;
#pragma unroll
            for (int q = 0; q < 4; q++) {
                float f = wf[q], h = tf32r(f);
                wh[wrow][wcol + q] = h; wl[wrow][wcol + q] = f - h;
            }
        }
        __syncthreads();

#pragma unroll
        for (int kk2 = 0; kk2 < 2; kk2++) {
            const int kb = kk2 * 8;
            const uint32_t ah0 = fbits(xh[kb + c    ][mb + g]);
            const uint32_t ah1 = fbits(xh[kb + c    ][mb + g + 8]);
            const uint32_t ah2 = fbits(xh[kb + c + 4][mb + g]);
            const uint32_t ah3 = fbits(xh[kb + c + 4][mb + g + 8]);
            const uint32_t al0 = fbits(xl[kb + c    ][mb + g]);
            const uint32_t al1 = fbits(xl[kb + c    ][mb + g + 8]);
            const uint32_t al2 = fbits(xl[kb + c + 4][mb + g]);
            const uint32_t al3 = fbits(xl[kb + c + 4][mb + g + 8]);
#pragma unroll
            for (int nt = 0; nt < 8; nt++) {
                const uint32_t bh0 = fbits(wh[kb + c    ][nt * 8 + g]);
                const uint32_t bh1 = fbits(wh[kb + c + 4][nt * 8 + g]);
                const uint32_t bl0 = fbits(wl[kb + c    ][nt * 8 + g]);
                const uint32_t bl1 = fbits(wl[kb + c + 4][nt * 8 + g]);
                mma8(D[nt], ah0, ah1, ah2, ah3, bh0, bh1);
                mma8(D[nt], ah0, ah1, ah2, ah3, bl0, bl1);
                mma8(D[nt], al0, al1, al2, al3, bh0, bh1);
            }
        }
    }

    // epilogue: normal g_h + transposed tf32-rounded g_hTr
    const int bq   = m0 / N_;            // batch
    const int head = blockIdx.y;         // n0 = head*64
    const int nb   = (m0 % N_) + mb;     // node base for this warp
    float* hTb = g_hTr + (size_t)((bq * H_ + head) * FO_) * N_;

#pragma unroll
    for (int nt = 0; nt < 8; nt++) {
        const size_t r0 = (size_t)(m0 + mb + g)     * HF + n0 + nt * 8 + c * 2;
        const size_t r1 = (size_t)(m0 + mb + g + 8) * HF + n0 + nt * 8 + c * 2;
        *(float2*)(g_h + r0) = make_float2(D[nt][0], D[nt][1]);
        *(float2*)(g_h + r1) = make_float2(D[nt][2], D[nt][3]);

        const int f0 = nt * 8 + c * 2;
        hTb[(size_t)(f0)     * N_ + nb + g]     = tf32r(D[nt][0]);
        hTb[(size_t)(f0 + 1) * N_ + nb + g]     = tf32r(D[nt][1]);
        hTb[(size_t)(f0)     * N_ + nb + g + 8] = tf32r(D[nt][2]);
        hTb[(size_t)(f0 + 1) * N_ + nb + g + 8] = tf32r(D[nt][3]);
    }
}

// ---------------- Kernel 2: attention coefficients -> exp factors ----------------
// Max-form needs only A1 = e^s, A2 = e^{0.2 s}, E1 = e^d, E2 = e^{0.2 d}.
__global__ __launch_bounds__(256) void attn_coef_kernel(const float* __restrict__ a_src,
                                                        const float* __restrict__ a_dst) {
    const int nh   = (blockIdx.x * blockDim.x + threadIdx.x) >> 5;
    const int lane = threadIdx.x & 31;
    if (nh >= NH) return;
    const int head = nh & (H_ - 1);

    const float* hrow = g_h + (size_t)nh * FO_;
    const float v0 = hrow[lane];
    const float v1 = hrow[lane + 32];
    const float* as = a_src + head * FO_;
    const float* ad = a_dst + head * FO_;
    float ps = v0 * as[lane] + v1 * as[lane + 32];
    float pd = v0 * ad[lane] + v1 * ad[lane + 32];
#pragma unroll
    for (int o = 16; o > 0; o >>= 1) {
        ps += __shfl_xor_sync(0xffffffffu, ps, o);
        pd += __shfl_xor_sync(0xffffffffu, pd, o);
    }
    if (lane == 0) {
        g_A1[nh] = expf(ps);
        g_A2[nh] = expf(0.2f * ps);
        g_E1[nh] = expf(pd);
        g_E2[nh] = expf(0.2f * pd);
    }
}

// ---------------- Kernel 3: split-j mma.sync tf32 attention ----------------
// Block = (i-block 128, head, b*SPLIT + seg), 128 threads = 4 warps.
// Max-form weights: w_ij = max(A1_i*E1_j, A2_i*E2_j), masked by adj bit.
// NO explicit tf32 rounding: the mma unit truncates the SAME A registers for
// both the numerator and the ones-column denominator -> exact consistency.
// h-tile TRANSPOSED: h_sT[f][j] -> B-frags via LDS.128 (2 k-steps per load).
#define TJ  32
#define HST 36     // h_sT row stride (floats): 32 j + 4 pad

__global__ __launch_bounds__(128, 3) void gat_attn_mma(void) {
    __shared__ __align__(16) float h_sT[64][HST];
    __shared__ __align__(8) float2 de_s[TJ];    // {E1, E2} per j
    __shared__ uint32_t bm_s[128];

    const int t    = threadIdx.x;
    const int wi   = t >> 5;
    const int lane = t & 31;
    const int g    = lane >> 2;    // groupID 0..7
    const int c    = lane & 3;     // threadID_in_group 0..3
    const int ib   = blockIdx.x;
    const int head = blockIdx.y;
    const int b    = blockIdx.z >> 2;     // SPLIT = 4
    const int seg  = blockIdx.z & 3;
    const int jt0  = seg * TPS;

    // per-thread row coefficients: rr -> row wi*32 + (rr>>1)*16 + (rr&1)*8 + g
    float A1[4], A2[4];
#pragma unroll
    for (int rr = 0; rr < 4; rr++) {
        const int row = ib * 128 + wi * 32 + (rr >> 1) * 16 + (rr & 1) * 8 + g;
        const int nh  = (b * N_ + row) * H_ + head;
        A1[rr] = g_A1[nh]; A2[rr] = g_A2[nh];
    }

    float D[2][9][4];
#pragma unroll
    for (int mt = 0; mt < 2; mt++)
#pragma unroll
        for (int nt = 0; nt < 9; nt++)
#pragma unroll
            for (int q = 0; q < 4; q++) D[mt][nt][q] = 0.f;

    const float* hTb = g_hTr + (size_t)((b * H_ + head) * FO_) * N_;

    // transposed staging map: thread t -> f rows (t>>3)+16k, j-quad (t&7)*4
    const int fr = t >> 3;
    const int jq = (t & 7) * 4;

    // prologue: prefetch first tile of this segment
    uint32_t bmr;
    float4 hb[4];
    float ne1 = 0.f, ne2 = 0.f;
    {
        bmr = g_bitsT[jt0 * N_ + ib * 128 + t];
        const int j0 = jt0 * TJ;
#pragma unroll
        for (int k = 0; k < 4; k++)
            hb[k] = *(const float4*)(hTb + (size_t)(fr + 16 * k) * N_ + j0 + jq);
        if (t < TJ) {
            const int nh_j = (b * N_ + j0 + t) * H_ + head;
            ne1 = g_E1[nh_j]; ne2 = g_E2[nh_j];
        }
    }

    const uint32_t ONE = 0x3f800000u;

    for (int jl = 0; jl < TPS; jl++) {
        const int jt = jt0 + jl;
        __syncthreads();   // previous tile's compute done reading smem
        bm_s[t] = bmr;
#pragma unroll
        for (int k = 0; k < 4; k++)
            *(float4*)&h_sT[fr + 16 * k][jq] = hb[k];
        if (t < TJ) de_s[t] = make_float2(ne1, ne2);
        __syncthreads();

        // prefetch next tile (LDG latency hidden under Phase B + mma)
        if (jl + 1 < TPS) {
            const int j0 = (jt + 1) * TJ;
            bmr = g_bitsT[(jt + 1) * N_ + ib * 128 + t];
#pragma unroll
            for (int k = 0; k < 4; k++)
                hb[k] = *(const float4*)(hTb + (size_t)(fr + 16 * k) * N_ + j0 + jq);
            if (t < TJ) {
                const int nh_j = (b * N_ + j0 + t) * H_ + head;
                ne1 = g_E1[nh_j]; ne2 = g_E2[nh_j];
            }
        }

        // ---- Phase B: max-form weights into A-fragment registers ----
        // thread's j set: j = c*8 + u, u = 0..7
        float2 der[8];
#pragma unroll
        for (int u = 0; u < 8; u++) der[u] = de_s[c * 8 + u];

        float wv[4][8];
#pragma unroll
        for (int rr = 0; rr < 4; rr++) {
            const int rl = wi * 32 + (rr >> 1) * 16 + (rr & 1) * 8 + g;
            const uint32_t m = bm_s[rl] >> (c * 8);
#pragma unroll
            for (int u = 0; u < 8; u++) {
                const float w = fmaxf(A1[rr] * der[u].x, A2[rr] * der[u].y);
                wv[rr][u] = ((m >> u) & 1u) ? w : 0.f;
            }
        }

        // ---- mma phase: p covers k-steps s=2p, 2p+1 with ONE LDS.128 per nt ----
#pragma unroll
        for (int p = 0; p < 2; p++) {
            const uint32_t s0a00 = fbits(wv[0][4 * p]);
            const uint32_t s0a01 = fbits(wv[1][4 * p]);
            const uint32_t s0a02 = fbits(wv[0][4 * p + 1]);
            const uint32_t s0a03 = fbits(wv[1][4 * p + 1]);
            const uint32_t s0a10 = fbits(wv[2][4 * p]);
            const uint32_t s0a11 = fbits(wv[3][4 * p]);
            const uint32_t s0a12 = fbits(wv[2][4 * p + 1]);
            const uint32_t s0a13 = fbits(wv[3][4 * p + 1]);
            const uint32_t s1a00 = fbits(wv[0][4 * p + 2]);
            const uint32_t s1a01 = fbits(wv[1][4 * p + 2]);
            const uint32_t s1a02 = fbits(wv[0][4 * p + 3]);
            const uint32_t s1a03 = fbits(wv[1][4 * p + 3]);
            const uint32_t s1a10 = fbits(wv[2][4 * p + 2]);
            const uint32_t s1a11 = fbits(wv[3][4 * p + 2]);
            const uint32_t s1a12 = fbits(wv[2][4 * p + 3]);
            const uint32_t s1a13 = fbits(wv[3][4 * p + 3]);

#pragma unroll
            for (int nt = 0; nt < 8; nt++) {
                const float4 hv = *(const float4*)&h_sT[nt * 8 + g][c * 8 + 4 * p];
                mma8(D[0][nt], s0a00, s0a01, s0a02, s0a03, fbits(hv.x), fbits(hv.y));
                mma8(D[1][nt], s0a10, s0a11, s0a12, s0a13, fbits(hv.x), fbits(hv.y));
                mma8(D[0][nt], s1a00, s1a01, s1a02, s1a03, fbits(hv.z), fbits(hv.w));
                mma8(D[1][nt], s1a10, s1a11, s1a12, s1a13, fbits(hv.z), fbits(hv.w));
            }
            // denominator: B = 1 (constant, no LDS); same A regs -> exact consistency
            mma8(D[0][8], s0a00, s0a01, s0a02, s0a03, ONE, ONE);
            mma8(D[1][8], s0a10, s0a11, s0a12, s0a13, ONE, ONE);
            mma8(D[0][8], s1a00, s1a01, s1a02, s1a03, ONE, ONE);
            mma8(D[1][8], s1a10, s1a11, s1a12, s1a13, ONE, ONE);
        }
    }

    // ---- epilogue: write UNNORMALIZED partials to scratch ----
    const int pidx = ((b * H_ + head) * 16 + ib) * SPLIT + seg;
    float* pnum = g_pnum + (size_t)pidx * (128 * 64);
    float* pden = g_pden + (size_t)pidx * 128;

    if (c == 0) {
        pden[wi * 32 + g]      = D[0][8][0];
        pden[wi * 32 + g + 8]  = D[0][8][2];
        pden[wi * 32 + 16 + g] = D[1][8][0];
        pden[wi * 32 + 24 + g] = D[1][8][2];
    }

#pragma unroll
    for (int mt = 0; mt < 2; mt++)
#pragma unroll
        for (int hi = 0; hi < 2; hi++) {
            const int rl = wi * 32 + mt * 16 + hi * 8 + g;
            float* prow  = pnum + (size_t)rl * 64;
#pragma unroll
            for (int nt = 0; nt < 8; nt++) {
                float2 v;
                v.x = D[mt][nt][hi * 2];
                v.y = D[mt][nt][hi * 2 + 1];
                *(float2*)(prow + nt * 8 + 2 * c) = v;
            }
        }
}

// ---------------- Kernel 4: combine split partials + normalize ----------------
__global__ __launch_bounds__(256) void gat_combine(float* __restrict__ out) {
    const int t    = threadIdx.x;
    const int ib   = blockIdx.x;
    const int head = blockIdx.y;
    const int b    = blockIdx.z;
    const int row  = t >> 1;
    const int ch   = (t & 1) * 32;

    const int base = ((b * H_ + head) * 16 + ib) * SPLIT;

    float den = 0.f;
#pragma unroll
    for (int s = 0; s < SPLIT; s++)
        den += g_pden[(size_t)(base + s) * 128 + row];
    const float r = 1.0f / den;

    float4 acc[8];
#pragma unroll
    for (int q = 0; q < 8; q++) acc[q] = make_float4(0.f, 0.f, 0.f, 0.f);
#pragma unroll
    for (int s = 0; s < SPLIT; s++) {
        const float4* p = (const float4*)(g_pnum + (size_t)(base + s) * (128 * 64)
                                          + (size_t)row * 64 + ch);
#pragma unroll
        for (int q = 0; q < 8; q++) {
            const float4 v = p[q];
            acc[q].x += v.x; acc[q].y += v.y; acc[q].z += v.z; acc[q].w += v.w;
        }
    }

    float* orow = out + (size_t)(b * N_ + ib * 128 + row) * HF + head * FO_ + ch;
#pragma unroll
    for (int q = 0; q < 8; q++)
        *(float4*)(orow + 4 * q) = make_float4(acc[q].x * r, acc[q].y * r,
                                               acc[q].z * r, acc[q].w * r);
}

// ---------------- launch ----------------
extern "C" void kernel_launch(void* const* d_in, const int* in_sizes, int n_in,
                              void* d_out, int out_size) {
    (void)in_sizes; (void)n_in; (void)out_size;
    const float* x     = (const float*)d_in[0];
    const float* adj   = (const float*)d_in[1];
    const float* W     = (const float*)d_in[2];
    const float* a_src = (const float*)d_in[3];
    const float* a_dst = (const float*)d_in[4];
    float* out = (float*)d_out;

    adj_pack_kernel<<<(N_ * 32) / 256, 256>>>(adj);
    gemm_mma<<<dim3(M_ / 128, HF / 64), 256>>>(x, W);
    attn_coef_kernel<<<(NH * 32) / 256, 256>>>(a_src, a_dst);
    gat_attn_mma<<<dim3(N_ / 128, H_, B_ * SPLIT), 128>>>();
    gat_combine<<<dim3(16, H_, B_), 256>>>(out);
}